// round 14
// baseline (speedup 1.0000x reference)
#include <cuda_runtime.h>
#include <cuda_fp16.h>

#define HH 512
#define WW 512
#define TX 26                    // output cols per tile (26 + 6 halo = 32 lanes)
#define TY 32
#define NTX 20                   // ceil(512 / 26)
#define NTH 320                  // 10 warps; warp w = strip row w, lane = gate col
#define RXW 44                   // res word columns, base bx = (ox-8) & ~3
#define PR 21                    // pair-rows: 42 rows (y: oy-4 .. oy+37) / 2

// shifted[i,j] = src[i+di, j+dj]
__device__ __constant__ int c_di[8] = { 1, 1, 1, 0, 0, -1, -1, -1 };
__device__ __constant__ int c_dj[8] = { 1, 0,-1, 1,-1,  1,  0, -1 };

#define DI0 1
#define DI1 1
#define DI2 1
#define DI3 0
#define DI4 0
#define DI5 (-1)
#define DI6 (-1)
#define DI7 (-1)
#define DJ0 1
#define DJ1 0
#define DJ2 (-1)
#define DJ3 1
#define DJ4 (-1)
#define DJ5 1
#define DJ6 0
#define DJ7 (-1)

__device__ __forceinline__ unsigned int pack2(float lo, float hi) {
    __half2 h = __floats2half2_rn(lo, hi);       // single F2FP.PACK
    return *reinterpret_cast<unsigned int*>(&h);
}
__device__ __forceinline__ float2 unpack2(unsigned int w) {
    __half2 h;
    *reinterpret_cast<unsigned int*>(&h) = w;
    return __half22float2(h);
}

__device__ __forceinline__ float4 ld4_guard(const float* __restrict__ plane,
                                            int gy, int gx)
{
    float4 v = make_float4(0.f, 0.f, 0.f, 0.f);
    if ((unsigned)gy < HH) {
        const float* __restrict__ row = plane + (size_t)gy * WW;
        if ((unsigned)gx <= (unsigned)(WW - 4)) {
            v = *reinterpret_cast<const float4*>(row + gx);   // gx ≡ 0 mod 4
        } else {
            if ((unsigned)(gx + 0) < WW) v.x = __ldg(row + gx + 0);
            if ((unsigned)(gx + 1) < WW) v.y = __ldg(row + gx + 1);
            if ((unsigned)(gx + 2) < WW) v.z = __ldg(row + gx + 2);
            if ((unsigned)(gx + 3) < WW) v.w = __ldg(row + gx + 3);
        }
    }
    return v;
}

// One propagation step for a 4-row strip (fp16 exchange, fp32 math).
// Gates are UNNORMALIZED; inva is folded in at the end of each row's chain.
__device__ __forceinline__ void prop_step(const unsigned int* __restrict__ rc,
                                          int p0, int rx,
                                          const float g[4][8],
                                          const float bias[4],
                                          float inva,
                                          float val[4])
{
    const __half* __restrict__ rch = reinterpret_cast<const __half*>(rc);
    float2 a0 = unpack2(rc[(p0 + 0) * RXW + rx - 1]);
    float2 a1 = unpack2(rc[(p0 + 1) * RXW + rx - 1]);
    float2 a2 = unpack2(rc[(p0 + 2) * RXW + rx - 1]);
    float2 b0 = unpack2(rc[(p0 + 0) * RXW + rx + 1]);
    float2 b1 = unpack2(rc[(p0 + 1) * RXW + rx + 1]);
    float2 b2 = unpack2(rc[(p0 + 2) * RXW + rx + 1]);
    float L[6] = { a0.x, a0.y, a1.x, a1.y, a2.x, a2.y };
    float R[6] = { b0.x, b0.y, b1.x, b1.y, b2.x, b2.y };
    float C[6];
    C[0] = __half2float(rch[((p0 + 0) * RXW + rx) * 2 + 0]);   // row 4sy
    C[5] = __half2float(rch[((p0 + 2) * RXW + rx) * 2 + 1]);   // row 4sy+5
    C[1] = val[0]; C[2] = val[1]; C[3] = val[2]; C[4] = val[3];

    float nv[4];
    #pragma unroll
    for (int r = 0; r < 4; r++) {
        float s;
        s  = g[r][0] * R[r + 2];
        s += g[r][1] * C[r + 2];
        s += g[r][2] * L[r + 2];
        s += g[r][3] * R[r + 1];
        s += g[r][4] * L[r + 1];
        s += g[r][5] * R[r];
        s += g[r][6] * C[r];
        s += g[r][7] * L[r];
        nv[r] = fmaf(inva, s, bias[r]);
    }
    #pragma unroll
    for (int r = 0; r < 4; r++) val[r] = nv[r];
}

// Store a strip's 4 values into buffer rn (byte-granular at shared words).
__device__ __forceinline__ void strip_store(unsigned int* __restrict__ rn,
                                            int p0, int rx, const float val[4])
{
    __half* __restrict__ rh = reinterpret_cast<__half*>(rn);
    rh[((p0 + 0) * RXW + rx) * 2 + 1] = __float2half_rn(val[0]);  // row 4sy+1 (hi)
    rn[(p0 + 1) * RXW + rx] = pack2(val[1], val[2]);              // rows 4sy+2,3
    rh[((p0 + 2) * RXW + rx) * 2 + 0] = __float2half_rn(val[3]);  // row 4sy+4 (lo)
}

__global__ __launch_bounds__(NTH, 4)
void affinity_fused(const float* __restrict__ guid,
                    const float* __restrict__ blur,
                    float* __restrict__ out)
{
    // fp16 exchange buffers: word (p, c) = half2(row 2p, row 2p+1) at col c
    __shared__ unsigned int res[2][PR * RXW];

    const int tid = threadIdx.x;
    const int b   = blockIdx.z;
    const int txi = blockIdx.x;
    const int tyi = blockIdx.y;
    const int ox  = txi * TX;
    const int oy  = tyi * TY;
    const bool edge = (txi == 0) | (txi == NTX - 1) | (tyi == 0) | (tyi == 15);

    const float* __restrict__ blurb = blur + (size_t)b * HH * WW;
    const float* __restrict__ guidb = guid + (size_t)b * 8 * HH * WW;

    // ---- Strip mapping: warp = strip row, lane = gate column (contiguous) ----
    const int sy   = tid >> 5;            // 0..9
    const int sx   = tid & 31;            // gate col 0..31
    const int x    = ox - 3 + sx;         // global x of strip
    const int y0   = oy - 3 + sy * 4;     // global y of strip top
    const int bx   = (ox - 8) & ~3;       // res base col (float4 aligned)
    const int rx   = (ox - 3 - bx) + sx;  // res col index
    const int p0   = 2 * sy;              // first pair-row of strip

    float g[4][8];
    float raw[4];

    if (!edge) {
        // ============== interior fast path (no guards) ==============
        {
            const float* __restrict__ gb = guidb + (size_t)y0 * WW + x;
            #pragma unroll
            for (int r = 0; r < 4; r++) {
                const float* __restrict__ gr = gb + r * WW;
                g[r][0] = __ldg(gr + 0 * HH * WW + DI0 * WW + DJ0);
                g[r][1] = __ldg(gr + 1 * HH * WW + DI1 * WW + DJ1);
                g[r][2] = __ldg(gr + 2 * HH * WW + DI2 * WW + DJ2);
                g[r][3] = __ldg(gr + 3 * HH * WW + DI3 * WW + DJ3);
                g[r][4] = __ldg(gr + 4 * HH * WW + DI4 * WW + DJ4);
                g[r][5] = __ldg(gr + 5 * HH * WW + DI5 * WW + DJ5);
                g[r][6] = __ldg(gr + 6 * HH * WW + DI6 * WW + DJ6);
                g[r][7] = __ldg(gr + 7 * HH * WW + DI7 * WW + DJ7);
            }
            const float* __restrict__ rb = blurb + (size_t)y0 * WW + x;
            raw[0] = __ldg(rb + 0 * WW);
            raw[1] = __ldg(rb + 1 * WW);
            raw[2] = __ldg(rb + 2 * WW);
            raw[3] = __ldg(rb + 3 * WW);
        }
        // Full-tile init of buf0 (coalesced float4; 231 items < 320 threads)
        if (tid < PR * 11) {
            int p = tid / 11, q = tid % 11;
            const float* __restrict__ base =
                blurb + (size_t)(oy - 4 + 2 * p) * WW + bx + 4 * q;
            float4 a  = *reinterpret_cast<const float4*>(base);
            float4 bb = *reinterpret_cast<const float4*>(base + WW);
            int o = p * RXW + 4 * q;
            res[0][o+0] = pack2(a.x, bb.x);
            res[0][o+1] = pack2(a.y, bb.y);
            res[0][o+2] = pack2(a.z, bb.z);
            res[0][o+3] = pack2(a.w, bb.w);
        }
        // buf1 caps: only pair-rows 0 and 20 are read before being overwritten
        if (tid < 2 * 11) {
            int p = (tid < 11) ? 0 : (PR - 1);
            int q = (tid < 11) ? tid : (tid - 11);
            const float* __restrict__ base =
                blurb + (size_t)(oy - 4 + 2 * p) * WW + bx + 4 * q;
            float4 a  = *reinterpret_cast<const float4*>(base);
            float4 bb = *reinterpret_cast<const float4*>(base + WW);
            int o = p * RXW + 4 * q;
            res[1][o+0] = pack2(a.x, bb.x);
            res[1][o+1] = pack2(a.y, bb.y);
            res[1][o+2] = pack2(a.z, bb.z);
            res[1][o+3] = pack2(a.w, bb.w);
        }
    } else {
        // ======== edge path: clamped addresses + float masks ========
        const int xc = min(max(x, 0), WW - 1);
        #pragma unroll
        for (int r = 0; r < 4; r++) {
            int y  = y0 + r;
            int yc = min(max(y, 0), HH - 1);
            bool pin = ((unsigned)y < HH) & ((unsigned)x < WW);
            float rv = __ldg(&blurb[(size_t)yc * WW + xc]);
            raw[r] = pin ? rv : 0.0f;
            #pragma unroll
            for (int k = 0; k < 8; k++) {
                int yy = y + c_di[k];
                int xx = x + c_dj[k];
                int yyc = min(max(yy, 0), HH - 1);
                int xxc = min(max(xx, 0), WW - 1);
                float v = __ldg(&guidb[((size_t)k * HH + yyc) * WW + xxc]);
                bool m = pin & ((unsigned)yy < HH) & ((unsigned)xx < WW);
                g[r][k] = m ? v : 0.0f;
            }
        }
        if (tid < PR * 11) {
            int p = tid / 11, q = tid % 11;
            float4 a  = ld4_guard(blurb, oy - 4 + 2 * p, bx + 4 * q);
            float4 bb = ld4_guard(blurb, oy - 3 + 2 * p, bx + 4 * q);
            int o = p * RXW + 4 * q;
            res[0][o+0] = pack2(a.x, bb.x);
            res[0][o+1] = pack2(a.y, bb.y);
            res[0][o+2] = pack2(a.z, bb.z);
            res[0][o+3] = pack2(a.w, bb.w);
        }
        if (tid < 2 * 11) {
            int p = (tid < 11) ? 0 : (PR - 1);
            int q = (tid < 11) ? tid : (tid - 11);
            float4 a  = ld4_guard(blurb, oy - 4 + 2 * p, bx + 4 * q);
            float4 bb = ld4_guard(blurb, oy - 3 + 2 * p, bx + 4 * q);
            int o = p * RXW + 4 * q;
            res[1][o+0] = pack2(a.x, bb.x);
            res[1][o+1] = pack2(a.y, bb.y);
            res[1][o+2] = pack2(a.z, bb.z);
            res[1][o+3] = pack2(a.w, bb.w);
        }
    }

    // ---- gate prep: gates stay unnormalized; inva folded per iteration ----
    // Per-pixel inva differs by row, so keep inva per row packed in bias path:
    // bias[r] = (1 - gs_r) * raw_r with gs_r = (sum g)*inva_r; val seeds raw.
    float bias[4], val[4], inva[4];
    #pragma unroll
    for (int r = 0; r < 4; r++) {
        float a = 0.f;
        #pragma unroll
        for (int k = 0; k < 8; k++) a += fabsf(g[r][k]);
        float ia = (a > 0.f) ? __fdividef(1.0f, a) : 0.0f;
        float gsum = 0.f;
        #pragma unroll
        for (int k = 0; k < 8; k++) gsum += g[r][k];
        inva[r] = ia;
        bias[r] = (1.0f - gsum * ia) * raw[r];
        val[r]  = raw[r];
    }
    __syncthreads();

    // ---- iterations 0..2: compute, store, barrier (all threads are strips) ----
    #pragma unroll
    for (int t = 0; t < 3; t++) {
        {
            // inva varies per row: inline the per-row fold
            const unsigned int* __restrict__ rc = res[t & 1];
            const __half* __restrict__ rch = reinterpret_cast<const __half*>(rc);
            float2 a0 = unpack2(rc[(p0 + 0) * RXW + rx - 1]);
            float2 a1 = unpack2(rc[(p0 + 1) * RXW + rx - 1]);
            float2 a2 = unpack2(rc[(p0 + 2) * RXW + rx - 1]);
            float2 b0 = unpack2(rc[(p0 + 0) * RXW + rx + 1]);
            float2 b1 = unpack2(rc[(p0 + 1) * RXW + rx + 1]);
            float2 b2 = unpack2(rc[(p0 + 2) * RXW + rx + 1]);
            float L[6] = { a0.x, a0.y, a1.x, a1.y, a2.x, a2.y };
            float R[6] = { b0.x, b0.y, b1.x, b1.y, b2.x, b2.y };
            float C[6];
            C[0] = __half2float(rch[((p0 + 0) * RXW + rx) * 2 + 0]);
            C[5] = __half2float(rch[((p0 + 2) * RXW + rx) * 2 + 1]);
            C[1] = val[0]; C[2] = val[1]; C[3] = val[2]; C[4] = val[3];
            float nv[4];
            #pragma unroll
            for (int r = 0; r < 4; r++) {
                float s;
                s  = g[r][0] * R[r + 2];
                s += g[r][1] * C[r + 2];
                s += g[r][2] * L[r + 2];
                s += g[r][3] * R[r + 1];
                s += g[r][4] * L[r + 1];
                s += g[r][5] * R[r];
                s += g[r][6] * C[r];
                s += g[r][7] * L[r];
                nv[r] = fmaf(inva[r], s, bias[r]);
            }
            #pragma unroll
            for (int r = 0; r < 4; r++) val[r] = nv[r];
        }
        strip_store(res[(t & 1) ^ 1], p0, rx, val);
        __syncthreads();
    }

    // ---- final iteration + output: only warps whose values are read ----
    if (sy < 9) {
        const unsigned int* __restrict__ rc = res[1];
        const __half* __restrict__ rch = reinterpret_cast<const __half*>(rc);
        float2 a0 = unpack2(rc[(p0 + 0) * RXW + rx - 1]);
        float2 a1 = unpack2(rc[(p0 + 1) * RXW + rx - 1]);
        float2 a2 = unpack2(rc[(p0 + 2) * RXW + rx - 1]);
        float2 b0 = unpack2(rc[(p0 + 0) * RXW + rx + 1]);
        float2 b1 = unpack2(rc[(p0 + 1) * RXW + rx + 1]);
        float2 b2 = unpack2(rc[(p0 + 2) * RXW + rx + 1]);
        float L[6] = { a0.x, a0.y, a1.x, a1.y, a2.x, a2.y };
        float R[6] = { b0.x, b0.y, b1.x, b1.y, b2.x, b2.y };
        float C[6];
        C[0] = __half2float(rch[((p0 + 0) * RXW + rx) * 2 + 0]);
        C[5] = __half2float(rch[((p0 + 2) * RXW + rx) * 2 + 1]);
        C[1] = val[0]; C[2] = val[1]; C[3] = val[2]; C[4] = val[3];
        float nv[4];
        #pragma unroll
        for (int r = 0; r < 4; r++) {
            float s;
            s  = g[r][0] * R[r + 2];
            s += g[r][1] * C[r + 2];
            s += g[r][2] * L[r + 2];
            s += g[r][3] * R[r + 1];
            s += g[r][4] * L[r + 1];
            s += g[r][5] * R[r];
            s += g[r][6] * C[r];
            s += g[r][7] * L[r];
            nv[r] = fmaf(inva[r], s, bias[r]);
        }
        float* __restrict__ outb = out + (size_t)b * HH * WW;
        if (sx >= 3 && sx < 3 + TX && x < WW) {
            #pragma unroll
            for (int r = 0; r < 4; r++) {
                int gy = sy * 4 + r;
                if (gy >= 3 && gy < 3 + TY)     // uniform per warp
                    outb[(y0 + r) * WW + x] = nv[r];
            }
        }
    }
}

extern "C" void kernel_launch(void* const* d_in, const int* in_sizes, int n_in,
                              void* d_out, int out_size)
{
    const float* guid = (const float*)d_in[0];
    const float* blur = (const float*)d_in[1];
    int gsz = in_sizes[0];
    int bsz = in_sizes[1];
    if (n_in >= 2 && gsz < bsz) {   // defensive: handle swapped order
        const float* tmp = guid; guid = blur; blur = tmp;
        int t = gsz; gsz = bsz; bsz = t;
    }
    int batch = bsz / (HH * WW);

    dim3 grid(NTX, 16, batch);
    affinity_fused<<<grid, NTH>>>(guid, blur, (float*)d_out);
}

// round 15
// speedup vs baseline: 1.0829x; 1.0829x over previous
#include <cuda_runtime.h>
#include <cuda_fp16.h>

#define HH 512
#define WW 512
#define TX 26                    // output cols per tile (26 + 6 halo = 32 lanes)
#define TY 64
#define NTX 20                   // ceil(512 / 26)
#define NTY 8                    // 512 / 64
#define NSY 18                   // strip rows: gate rows 0..71 (66 needed + pad)
#define NTH (NSY * 32)           // 576 threads
#define RXW 44                   // res word columns, base bx = (ox-8) & ~3
#define PR 37                    // pair-rows: 74 rows (y: oy-4 .. oy+69) / 2

// shifted[i,j] = src[i+di, j+dj]
__device__ __constant__ int c_di[8] = { 1, 1, 1, 0, 0, -1, -1, -1 };
__device__ __constant__ int c_dj[8] = { 1, 0,-1, 1,-1,  1,  0, -1 };

#define DI0 1
#define DI1 1
#define DI2 1
#define DI3 0
#define DI4 0
#define DI5 (-1)
#define DI6 (-1)
#define DI7 (-1)
#define DJ0 1
#define DJ1 0
#define DJ2 (-1)
#define DJ3 1
#define DJ4 (-1)
#define DJ5 1
#define DJ6 0
#define DJ7 (-1)

__device__ __forceinline__ unsigned int pack2(float lo, float hi) {
    __half2 h = __floats2half2_rn(lo, hi);       // single F2FP.PACK
    return *reinterpret_cast<unsigned int*>(&h);
}
__device__ __forceinline__ float2 unpack2(unsigned int w) {
    __half2 h;
    *reinterpret_cast<unsigned int*>(&h) = w;
    return __half22float2(h);
}

__device__ __forceinline__ float4 ld4_guard(const float* __restrict__ plane,
                                            int gy, int gx)
{
    float4 v = make_float4(0.f, 0.f, 0.f, 0.f);
    if ((unsigned)gy < HH) {
        const float* __restrict__ row = plane + (size_t)gy * WW;
        if ((unsigned)gx <= (unsigned)(WW - 4)) {
            v = *reinterpret_cast<const float4*>(row + gx);   // gx ≡ 0 mod 4
        } else {
            if ((unsigned)(gx + 0) < WW) v.x = __ldg(row + gx + 0);
            if ((unsigned)(gx + 1) < WW) v.y = __ldg(row + gx + 1);
            if ((unsigned)(gx + 2) < WW) v.z = __ldg(row + gx + 2);
            if ((unsigned)(gx + 3) < WW) v.w = __ldg(row + gx + 3);
        }
    }
    return v;
}

// One propagation step for a 4-row strip (fp16 exchange, fp32 math).
__device__ __forceinline__ void prop_step(const unsigned int* __restrict__ rc,
                                          int p0, int rx,
                                          const float g[4][8],
                                          const float bias[4],
                                          float val[4])
{
    const __half* __restrict__ rch = reinterpret_cast<const __half*>(rc);
    float2 a0 = unpack2(rc[(p0 + 0) * RXW + rx - 1]);
    float2 a1 = unpack2(rc[(p0 + 1) * RXW + rx - 1]);
    float2 a2 = unpack2(rc[(p0 + 2) * RXW + rx - 1]);
    float2 b0 = unpack2(rc[(p0 + 0) * RXW + rx + 1]);
    float2 b1 = unpack2(rc[(p0 + 1) * RXW + rx + 1]);
    float2 b2 = unpack2(rc[(p0 + 2) * RXW + rx + 1]);
    float L[6] = { a0.x, a0.y, a1.x, a1.y, a2.x, a2.y };
    float R[6] = { b0.x, b0.y, b1.x, b1.y, b2.x, b2.y };
    float C[6];
    C[0] = __half2float(rch[((p0 + 0) * RXW + rx) * 2 + 0]);   // row 4sy
    C[5] = __half2float(rch[((p0 + 2) * RXW + rx) * 2 + 1]);   // row 4sy+5
    C[1] = val[0]; C[2] = val[1]; C[3] = val[2]; C[4] = val[3];

    float nv[4];
    #pragma unroll
    for (int r = 0; r < 4; r++) {
        float s = bias[r];
        s += g[r][0] * R[r + 2];
        s += g[r][1] * C[r + 2];
        s += g[r][2] * L[r + 2];
        s += g[r][3] * R[r + 1];
        s += g[r][4] * L[r + 1];
        s += g[r][5] * R[r];
        s += g[r][6] * C[r];
        s += g[r][7] * L[r];
        nv[r] = s;
    }
    #pragma unroll
    for (int r = 0; r < 4; r++) val[r] = nv[r];
}

// Store a strip's 4 values into buffer rn (byte-granular at shared words).
__device__ __forceinline__ void strip_store(unsigned int* __restrict__ rn,
                                            int p0, int rx, const float val[4])
{
    __half* __restrict__ rh = reinterpret_cast<__half*>(rn);
    rh[((p0 + 0) * RXW + rx) * 2 + 1] = __float2half_rn(val[0]);  // row 4sy+1 (hi)
    rn[(p0 + 1) * RXW + rx] = pack2(val[1], val[2]);              // rows 4sy+2,3
    rh[((p0 + 2) * RXW + rx) * 2 + 0] = __float2half_rn(val[3]);  // row 4sy+4 (lo)
}

__global__ __launch_bounds__(NTH, 2)
void affinity_fused(const float* __restrict__ guid,
                    const float* __restrict__ blur,
                    float* __restrict__ out)
{
    // fp16 exchange buffers: word (p, c) = half2(row 2p, row 2p+1) at col c
    __shared__ unsigned int res[2][PR * RXW];

    const int tid = threadIdx.x;
    const int b   = blockIdx.z;
    const int txi = blockIdx.x;
    const int tyi = blockIdx.y;
    const int ox  = txi * TX;
    const int oy  = tyi * TY;
    const bool edge = (txi == 0) | (txi == NTX - 1) | (tyi == 0) | (tyi == NTY - 1);

    const float* __restrict__ blurb = blur + (size_t)b * HH * WW;
    const float* __restrict__ guidb = guid + (size_t)b * 8 * HH * WW;

    // ---- Strip mapping: warp = strip row, lane = gate column (contiguous) ----
    const int sy   = tid >> 5;            // 0..17
    const int sx   = tid & 31;            // gate col 0..31
    const int x    = ox - 3 + sx;         // global x of strip
    const int y0   = oy - 3 + sy * 4;     // global y of strip top
    const int bx   = (ox - 8) & ~3;       // res base col (float4 aligned)
    const int rx   = (ox - 3 - bx) + sx;  // res col index
    const int p0   = 2 * sy;              // first pair-row of strip

    float g[4][8];
    float raw[4];

    if (!edge) {
        // ============== interior fast path (no guards) ==============
        // Gate + raw LDGs first: longest-latency loads front-loaded.
        {
            const float* __restrict__ gb = guidb + (size_t)y0 * WW + x;
            #pragma unroll
            for (int r = 0; r < 4; r++) {
                const float* __restrict__ gr = gb + r * WW;
                g[r][0] = __ldg(gr + 0 * HH * WW + DI0 * WW + DJ0);
                g[r][1] = __ldg(gr + 1 * HH * WW + DI1 * WW + DJ1);
                g[r][2] = __ldg(gr + 2 * HH * WW + DI2 * WW + DJ2);
                g[r][3] = __ldg(gr + 3 * HH * WW + DI3 * WW + DJ3);
                g[r][4] = __ldg(gr + 4 * HH * WW + DI4 * WW + DJ4);
                g[r][5] = __ldg(gr + 5 * HH * WW + DI5 * WW + DJ5);
                g[r][6] = __ldg(gr + 6 * HH * WW + DI6 * WW + DJ6);
                g[r][7] = __ldg(gr + 7 * HH * WW + DI7 * WW + DJ7);
            }
            const float* __restrict__ rb = blurb + (size_t)y0 * WW + x;
            raw[0] = __ldg(rb + 0 * WW);
            raw[1] = __ldg(rb + 1 * WW);
            raw[2] = __ldg(rb + 2 * WW);
            raw[3] = __ldg(rb + 3 * WW);
        }
        // Full-tile init of buf0 (coalesced float4; 407 items < 576 threads)
        if (tid < PR * 11) {
            int p = tid / 11, q = tid % 11;
            const float* __restrict__ base =
                blurb + (size_t)(oy - 4 + 2 * p) * WW + bx + 4 * q;
            float4 a  = *reinterpret_cast<const float4*>(base);
            float4 bb = *reinterpret_cast<const float4*>(base + WW);
            int o = p * RXW + 4 * q;
            res[0][o+0] = pack2(a.x, bb.x);
            res[0][o+1] = pack2(a.y, bb.y);
            res[0][o+2] = pack2(a.z, bb.z);
            res[0][o+3] = pack2(a.w, bb.w);
        }
        // buf1 caps: only pair-rows 0 and 36 are read before being overwritten
        if (tid < 2 * 11) {
            int p = (tid < 11) ? 0 : (PR - 1);
            int q = (tid < 11) ? tid : (tid - 11);
            const float* __restrict__ base =
                blurb + (size_t)(oy - 4 + 2 * p) * WW + bx + 4 * q;
            float4 a  = *reinterpret_cast<const float4*>(base);
            float4 bb = *reinterpret_cast<const float4*>(base + WW);
            int o = p * RXW + 4 * q;
            res[1][o+0] = pack2(a.x, bb.x);
            res[1][o+1] = pack2(a.y, bb.y);
            res[1][o+2] = pack2(a.z, bb.z);
            res[1][o+3] = pack2(a.w, bb.w);
        }
    } else {
        // ======== edge path: clamped addresses + float masks ========
        const int xc = min(max(x, 0), WW - 1);
        #pragma unroll
        for (int r = 0; r < 4; r++) {
            int y  = y0 + r;
            int yc = min(max(y, 0), HH - 1);
            bool pin = ((unsigned)y < HH) & ((unsigned)x < WW);
            float rv = __ldg(&blurb[(size_t)yc * WW + xc]);
            raw[r] = pin ? rv : 0.0f;
            #pragma unroll
            for (int k = 0; k < 8; k++) {
                int yy = y + c_di[k];
                int xx = x + c_dj[k];
                int yyc = min(max(yy, 0), HH - 1);
                int xxc = min(max(xx, 0), WW - 1);
                float v = __ldg(&guidb[((size_t)k * HH + yyc) * WW + xxc]);
                bool m = pin & ((unsigned)yy < HH) & ((unsigned)xx < WW);
                g[r][k] = m ? v : 0.0f;
            }
        }
        if (tid < PR * 11) {
            int p = tid / 11, q = tid % 11;
            float4 a  = ld4_guard(blurb, oy - 4 + 2 * p, bx + 4 * q);
            float4 bb = ld4_guard(blurb, oy - 3 + 2 * p, bx + 4 * q);
            int o = p * RXW + 4 * q;
            res[0][o+0] = pack2(a.x, bb.x);
            res[0][o+1] = pack2(a.y, bb.y);
            res[0][o+2] = pack2(a.z, bb.z);
            res[0][o+3] = pack2(a.w, bb.w);
        }
        if (tid < 2 * 11) {
            int p = (tid < 11) ? 0 : (PR - 1);
            int q = (tid < 11) ? tid : (tid - 11);
            float4 a  = ld4_guard(blurb, oy - 4 + 2 * p, bx + 4 * q);
            float4 bb = ld4_guard(blurb, oy - 3 + 2 * p, bx + 4 * q);
            int o = p * RXW + 4 * q;
            res[1][o+0] = pack2(a.x, bb.x);
            res[1][o+1] = pack2(a.y, bb.y);
            res[1][o+2] = pack2(a.z, bb.z);
            res[1][o+3] = pack2(a.w, bb.w);
        }
    }

    // ---- gate normalization (register-only -> hoisted before barrier) ----
    float bias[4], val[4];
    #pragma unroll
    for (int r = 0; r < 4; r++) {
        float a = 0.f;
        #pragma unroll
        for (int k = 0; k < 8; k++) a += fabsf(g[r][k]);
        float inva = (a > 0.f) ? __fdividef(1.0f, a) : 0.0f;
        float gs = 0.f;
        #pragma unroll
        for (int k = 0; k < 8; k++) { g[r][k] *= inva; gs += g[r][k]; }
        bias[r] = (1.0f - gs) * raw[r];
        val[r]  = raw[r];
    }
    __syncthreads();

    // ---- iterations 0..2: compute, store, barrier (all threads are strips) ----
    #pragma unroll
    for (int t = 0; t < 3; t++) {
        prop_step(res[t & 1], p0, rx, g, bias, val);
        strip_store(res[(t & 1) ^ 1], p0, rx, val);
        __syncthreads();
    }

    // ---- final iteration + output: only warps whose values are read ----
    // (strip row 17 = gate rows 68..71 -> no output rows; no barrier after t=3)
    if (sy < 17) {
        prop_step(res[1], p0, rx, g, bias, val);
        float* __restrict__ outb = out + (size_t)b * HH * WW;
        if (sx >= 3 && sx < 3 + TX && x < WW) {
            #pragma unroll
            for (int r = 0; r < 4; r++) {
                int gy = sy * 4 + r;
                if (gy >= 3 && gy < 3 + TY)     // uniform per warp
                    outb[(y0 + r) * WW + x] = val[r];
            }
        }
    }
}

extern "C" void kernel_launch(void* const* d_in, const int* in_sizes, int n_in,
                              void* d_out, int out_size)
{
    const float* guid = (const float*)d_in[0];
    const float* blur = (const float*)d_in[1];
    int gsz = in_sizes[0];
    int bsz = in_sizes[1];
    if (n_in >= 2 && gsz < bsz) {   // defensive: handle swapped order
        const float* tmp = guid; guid = blur; blur = tmp;
        int t = gsz; gsz = bsz; bsz = t;
    }
    int batch = bsz / (HH * WW);

    dim3 grid(NTX, NTY, batch);
    affinity_fused<<<grid, NTH>>>(guid, blur, (float*)d_out);
}

// round 16
// speedup vs baseline: 1.1695x; 1.0799x over previous
#include <cuda_runtime.h>
#include <cuda_fp16.h>

#define HH 512
#define WW 512
#define TX 26                    // output cols per tile (26 + 6 halo = 32 lanes)
#define TY 40                    // output rows per tile
#define NTX 20                   // ceil(512 / 26)
#define NTY 13                   // ceil(512 / 40)
#define NSY 12                   // strip rows (48 gate rows; 46 needed + pad)
#define NTH (NSY * 32)           // 384 threads, 12 warps
#define RXW 44                   // res word columns, base bx = (ox-8) & ~3
#define PR 25                    // pair-rows: 50 rows (y: oy-4 .. oy+45) / 2

// shifted[i,j] = src[i+di, j+dj]
__device__ __constant__ int c_di[8] = { 1, 1, 1, 0, 0, -1, -1, -1 };
__device__ __constant__ int c_dj[8] = { 1, 0,-1, 1,-1,  1,  0, -1 };

#define DI0 1
#define DI1 1
#define DI2 1
#define DI3 0
#define DI4 0
#define DI5 (-1)
#define DI6 (-1)
#define DI7 (-1)
#define DJ0 1
#define DJ1 0
#define DJ2 (-1)
#define DJ3 1
#define DJ4 (-1)
#define DJ5 1
#define DJ6 0
#define DJ7 (-1)

__device__ __forceinline__ unsigned int pack2(float lo, float hi) {
    __half2 h = __floats2half2_rn(lo, hi);       // single F2FP.PACK
    return *reinterpret_cast<unsigned int*>(&h);
}
__device__ __forceinline__ float2 unpack2(unsigned int w) {
    __half2 h;
    *reinterpret_cast<unsigned int*>(&h) = w;
    return __half22float2(h);
}

__device__ __forceinline__ float4 ld4_guard(const float* __restrict__ plane,
                                            int gy, int gx)
{
    float4 v = make_float4(0.f, 0.f, 0.f, 0.f);
    if ((unsigned)gy < HH) {
        const float* __restrict__ row = plane + (size_t)gy * WW;
        if ((unsigned)gx <= (unsigned)(WW - 4)) {
            v = *reinterpret_cast<const float4*>(row + gx);   // gx ≡ 0 mod 4
        } else {
            if ((unsigned)(gx + 0) < WW) v.x = __ldg(row + gx + 0);
            if ((unsigned)(gx + 1) < WW) v.y = __ldg(row + gx + 1);
            if ((unsigned)(gx + 2) < WW) v.z = __ldg(row + gx + 2);
            if ((unsigned)(gx + 3) < WW) v.w = __ldg(row + gx + 3);
        }
    }
    return v;
}

// One propagation step for a 4-row strip (fp16 exchange, fp32 math).
__device__ __forceinline__ void prop_step(const unsigned int* __restrict__ rc,
                                          int p0, int rx,
                                          const float g[4][8],
                                          const float bias[4],
                                          float val[4])
{
    const __half* __restrict__ rch = reinterpret_cast<const __half*>(rc);
    float2 a0 = unpack2(rc[(p0 + 0) * RXW + rx - 1]);
    float2 a1 = unpack2(rc[(p0 + 1) * RXW + rx - 1]);
    float2 a2 = unpack2(rc[(p0 + 2) * RXW + rx - 1]);
    float2 b0 = unpack2(rc[(p0 + 0) * RXW + rx + 1]);
    float2 b1 = unpack2(rc[(p0 + 1) * RXW + rx + 1]);
    float2 b2 = unpack2(rc[(p0 + 2) * RXW + rx + 1]);
    float L[6] = { a0.x, a0.y, a1.x, a1.y, a2.x, a2.y };
    float R[6] = { b0.x, b0.y, b1.x, b1.y, b2.x, b2.y };
    float C[6];
    C[0] = __half2float(rch[((p0 + 0) * RXW + rx) * 2 + 0]);   // row 4sy
    C[5] = __half2float(rch[((p0 + 2) * RXW + rx) * 2 + 1]);   // row 4sy+5
    C[1] = val[0]; C[2] = val[1]; C[3] = val[2]; C[4] = val[3];

    float nv[4];
    #pragma unroll
    for (int r = 0; r < 4; r++) {
        float s = bias[r];
        s += g[r][0] * R[r + 2];
        s += g[r][1] * C[r + 2];
        s += g[r][2] * L[r + 2];
        s += g[r][3] * R[r + 1];
        s += g[r][4] * L[r + 1];
        s += g[r][5] * R[r];
        s += g[r][6] * C[r];
        s += g[r][7] * L[r];
        nv[r] = s;
    }
    #pragma unroll
    for (int r = 0; r < 4; r++) val[r] = nv[r];
}

// Store a strip's 4 values into buffer rn (byte-granular at shared words).
__device__ __forceinline__ void strip_store(unsigned int* __restrict__ rn,
                                            int p0, int rx, const float val[4])
{
    __half* __restrict__ rh = reinterpret_cast<__half*>(rn);
    rh[((p0 + 0) * RXW + rx) * 2 + 1] = __float2half_rn(val[0]);  // row 4sy+1 (hi)
    rn[(p0 + 1) * RXW + rx] = pack2(val[1], val[2]);              // rows 4sy+2,3
    rh[((p0 + 2) * RXW + rx) * 2 + 0] = __float2half_rn(val[3]);  // row 4sy+4 (lo)
}

__global__ __launch_bounds__(NTH, 3)
void affinity_fused(const float* __restrict__ guid,
                    const float* __restrict__ blur,
                    float* __restrict__ out)
{
    // fp16 exchange buffers: word (p, c) = half2(row 2p, row 2p+1) at col c
    __shared__ unsigned int res[2][PR * RXW];

    const int tid = threadIdx.x;
    const int b   = blockIdx.z;
    const int txi = blockIdx.x;
    const int tyi = blockIdx.y;
    const int ox  = txi * TX;
    const int oy  = tyi * TY;
    const bool edge = (txi == 0) | (txi == NTX - 1) | (tyi == 0) | (tyi >= NTY - 2);
    // (tyi = 11 tile bottom halo reaches row 485 < 512, safe; tyi = 12 rows
    //  exceed the image -> edge path. tyi = 11 is kept interior: its res
    //  window max y = oy+45 = 485 < 512. Only tyi = 12 clips.)

    const float* __restrict__ blurb = blur + (size_t)b * HH * WW;
    const float* __restrict__ guidb = guid + (size_t)b * 8 * HH * WW;

    // ---- Strip mapping: warp = strip row, lane = gate column (contiguous) ----
    const int sy   = tid >> 5;            // 0..11
    const int sx   = tid & 31;            // gate col 0..31
    const int x    = ox - 3 + sx;         // global x of strip
    const int y0   = oy - 3 + sy * 4;     // global y of strip top
    const int bx   = (ox - 8) & ~3;       // res base col (float4 aligned)
    const int rx   = (ox - 3 - bx) + sx;  // res col index
    const int p0   = 2 * sy;              // first pair-row of strip

    float g[4][8];
    float raw[4];

    if (!edge) {
        // ============== interior fast path (no guards) ==============
        // Gate + raw LDGs first: longest-latency loads front-loaded.
        {
            const float* __restrict__ gb = guidb + (size_t)y0 * WW + x;
            #pragma unroll
            for (int r = 0; r < 4; r++) {
                const float* __restrict__ gr = gb + r * WW;
                g[r][0] = __ldg(gr + 0 * HH * WW + DI0 * WW + DJ0);
                g[r][1] = __ldg(gr + 1 * HH * WW + DI1 * WW + DJ1);
                g[r][2] = __ldg(gr + 2 * HH * WW + DI2 * WW + DJ2);
                g[r][3] = __ldg(gr + 3 * HH * WW + DI3 * WW + DJ3);
                g[r][4] = __ldg(gr + 4 * HH * WW + DI4 * WW + DJ4);
                g[r][5] = __ldg(gr + 5 * HH * WW + DI5 * WW + DJ5);
                g[r][6] = __ldg(gr + 6 * HH * WW + DI6 * WW + DJ6);
                g[r][7] = __ldg(gr + 7 * HH * WW + DI7 * WW + DJ7);
            }
            const float* __restrict__ rb = blurb + (size_t)y0 * WW + x;
            raw[0] = __ldg(rb + 0 * WW);
            raw[1] = __ldg(rb + 1 * WW);
            raw[2] = __ldg(rb + 2 * WW);
            raw[3] = __ldg(rb + 3 * WW);
        }
        // Full-tile init of buf0 (coalesced float4; 275 items < 384 threads)
        if (tid < PR * 11) {
            int p = tid / 11, q = tid % 11;
            const float* __restrict__ base =
                blurb + (size_t)(oy - 4 + 2 * p) * WW + bx + 4 * q;
            float4 a  = *reinterpret_cast<const float4*>(base);
            float4 bb = *reinterpret_cast<const float4*>(base + WW);
            int o = p * RXW + 4 * q;
            res[0][o+0] = pack2(a.x, bb.x);
            res[0][o+1] = pack2(a.y, bb.y);
            res[0][o+2] = pack2(a.z, bb.z);
            res[0][o+3] = pack2(a.w, bb.w);
        }
        // buf1 caps: only pair-rows 0 and 24 are read before being overwritten
        if (tid < 2 * 11) {
            int p = (tid < 11) ? 0 : (PR - 1);
            int q = (tid < 11) ? tid : (tid - 11);
            const float* __restrict__ base =
                blurb + (size_t)(oy - 4 + 2 * p) * WW + bx + 4 * q;
            float4 a  = *reinterpret_cast<const float4*>(base);
            float4 bb = *reinterpret_cast<const float4*>(base + WW);
            int o = p * RXW + 4 * q;
            res[1][o+0] = pack2(a.x, bb.x);
            res[1][o+1] = pack2(a.y, bb.y);
            res[1][o+2] = pack2(a.z, bb.z);
            res[1][o+3] = pack2(a.w, bb.w);
        }
    } else {
        // ======== edge path: clamped addresses + float masks ========
        const int xc = min(max(x, 0), WW - 1);
        #pragma unroll
        for (int r = 0; r < 4; r++) {
            int y  = y0 + r;
            int yc = min(max(y, 0), HH - 1);
            bool pin = ((unsigned)y < HH) & ((unsigned)x < WW);
            float rv = __ldg(&blurb[(size_t)yc * WW + xc]);
            raw[r] = pin ? rv : 0.0f;
            #pragma unroll
            for (int k = 0; k < 8; k++) {
                int yy = y + c_di[k];
                int xx = x + c_dj[k];
                int yyc = min(max(yy, 0), HH - 1);
                int xxc = min(max(xx, 0), WW - 1);
                float v = __ldg(&guidb[((size_t)k * HH + yyc) * WW + xxc]);
                bool m = pin & ((unsigned)yy < HH) & ((unsigned)xx < WW);
                g[r][k] = m ? v : 0.0f;
            }
        }
        if (tid < PR * 11) {
            int p = tid / 11, q = tid % 11;
            float4 a  = ld4_guard(blurb, oy - 4 + 2 * p, bx + 4 * q);
            float4 bb = ld4_guard(blurb, oy - 3 + 2 * p, bx + 4 * q);
            int o = p * RXW + 4 * q;
            res[0][o+0] = pack2(a.x, bb.x);
            res[0][o+1] = pack2(a.y, bb.y);
            res[0][o+2] = pack2(a.z, bb.z);
            res[0][o+3] = pack2(a.w, bb.w);
        }
        if (tid < 2 * 11) {
            int p = (tid < 11) ? 0 : (PR - 1);
            int q = (tid < 11) ? tid : (tid - 11);
            float4 a  = ld4_guard(blurb, oy - 4 + 2 * p, bx + 4 * q);
            float4 bb = ld4_guard(blurb, oy - 3 + 2 * p, bx + 4 * q);
            int o = p * RXW + 4 * q;
            res[1][o+0] = pack2(a.x, bb.x);
            res[1][o+1] = pack2(a.y, bb.y);
            res[1][o+2] = pack2(a.z, bb.z);
            res[1][o+3] = pack2(a.w, bb.w);
        }
    }

    // ---- gate normalization (register-only -> hoisted before barrier) ----
    float bias[4], val[4];
    #pragma unroll
    for (int r = 0; r < 4; r++) {
        float a = 0.f;
        #pragma unroll
        for (int k = 0; k < 8; k++) a += fabsf(g[r][k]);
        float inva = (a > 0.f) ? __fdividef(1.0f, a) : 0.0f;
        float gs = 0.f;
        #pragma unroll
        for (int k = 0; k < 8; k++) { g[r][k] *= inva; gs += g[r][k]; }
        bias[r] = (1.0f - gs) * raw[r];
        val[r]  = raw[r];
    }
    __syncthreads();

    // ---- iterations 0..2: compute, store, barrier (all threads are strips) ----
    #pragma unroll
    for (int t = 0; t < 3; t++) {
        prop_step(res[t & 1], p0, rx, g, bias, val);
        strip_store(res[(t & 1) ^ 1], p0, rx, val);
        __syncthreads();
    }

    // ---- final iteration + output: only warps whose values are read ----
    // (strip row 11 = gate rows 44..47 -> no output rows; no barrier after t=3)
    if (sy < 11) {
        prop_step(res[1], p0, rx, g, bias, val);
        float* __restrict__ outb = out + (size_t)b * HH * WW;
        if (sx >= 3 && sx < 3 + TX && x < WW) {
            #pragma unroll
            for (int r = 0; r < 4; r++) {
                int gy = sy * 4 + r;
                int y  = y0 + r;
                if (gy >= 3 && gy < 3 + TY && (unsigned)y < HH)
                    outb[y * WW + x] = val[r];
            }
        }
    }
}

extern "C" void kernel_launch(void* const* d_in, const int* in_sizes, int n_in,
                              void* d_out, int out_size)
{
    const float* guid = (const float*)d_in[0];
    const float* blur = (const float*)d_in[1];
    int gsz = in_sizes[0];
    int bsz = in_sizes[1];
    if (n_in >= 2 && gsz < bsz) {   // defensive: handle swapped order
        const float* tmp = guid; guid = blur; blur = tmp;
        int t = gsz; gsz = bsz; bsz = t;
    }
    int batch = bsz / (HH * WW);

    dim3 grid(NTX, NTY, batch);
    affinity_fused<<<grid, NTH>>>(guid, blur, (float*)d_out);
}

// round 17
// speedup vs baseline: 1.1801x; 1.0091x over previous
#include <cuda_runtime.h>
#include <cuda_fp16.h>

#define HH 512
#define WW 512
#define TX 26                    // output cols per tile (26 + 6 halo = 32 lanes)
#define TY 40                    // output rows per tile
#define NTX 20                   // ceil(512 / 26)
#define NTY 13                   // ceil(512 / 40)
#define NSY 12                   // strip rows (48 gate rows; 46 needed + pad)
#define NTH (NSY * 32)           // 384 threads, 12 warps
#define RXW 44                   // res word columns, base bx = (ox-8) & ~3
#define PR 25                    // pair-rows: 50 rows (y: oy-4 .. oy+45) / 2

// shifted[i,j] = src[i+di, j+dj]
__device__ __constant__ int c_di[8] = { 1, 1, 1, 0, 0, -1, -1, -1 };
__device__ __constant__ int c_dj[8] = { 1, 0,-1, 1,-1,  1,  0, -1 };

#define DI0 1
#define DI1 1
#define DI2 1
#define DI3 0
#define DI4 0
#define DI5 (-1)
#define DI6 (-1)
#define DI7 (-1)
#define DJ0 1
#define DJ1 0
#define DJ2 (-1)
#define DJ3 1
#define DJ4 (-1)
#define DJ5 1
#define DJ6 0
#define DJ7 (-1)

__device__ __forceinline__ unsigned int pack2(float lo, float hi) {
    __half2 h = __floats2half2_rn(lo, hi);       // single F2FP.PACK
    return *reinterpret_cast<unsigned int*>(&h);
}
__device__ __forceinline__ float2 unpack2(unsigned int w) {
    __half2 h;
    *reinterpret_cast<unsigned int*>(&h) = w;
    return __half22float2(h);
}

__device__ __forceinline__ float4 ld4_guard(const float* __restrict__ plane,
                                            int gy, int gx)
{
    float4 v = make_float4(0.f, 0.f, 0.f, 0.f);
    if ((unsigned)gy < HH) {
        const float* __restrict__ row = plane + (size_t)gy * WW;
        if ((unsigned)gx <= (unsigned)(WW - 4)) {
            v = *reinterpret_cast<const float4*>(row + gx);   // gx ≡ 0 mod 4
        } else {
            if ((unsigned)(gx + 0) < WW) v.x = __ldg(row + gx + 0);
            if ((unsigned)(gx + 1) < WW) v.y = __ldg(row + gx + 1);
            if ((unsigned)(gx + 2) < WW) v.z = __ldg(row + gx + 2);
            if ((unsigned)(gx + 3) < WW) v.w = __ldg(row + gx + 3);
        }
    }
    return v;
}

// One propagation step for a 4-row strip (fp16 exchange, fp32 math).
// Word indices are precomputed by the caller (hoisted out of the loop).
__device__ __forceinline__ void prop_step(const unsigned int* __restrict__ rc,
                                          int iL, int iR, int iC,
                                          const float g[4][8],
                                          const float bias[4],
                                          float val[4])
{
    const __half* __restrict__ rch = reinterpret_cast<const __half*>(rc);
    float2 a0 = unpack2(rc[iL]);
    float2 a1 = unpack2(rc[iL + RXW]);
    float2 a2 = unpack2(rc[iL + 2 * RXW]);
    float2 b0 = unpack2(rc[iR]);
    float2 b1 = unpack2(rc[iR + RXW]);
    float2 b2 = unpack2(rc[iR + 2 * RXW]);
    float L[6] = { a0.x, a0.y, a1.x, a1.y, a2.x, a2.y };
    float R[6] = { b0.x, b0.y, b1.x, b1.y, b2.x, b2.y };
    float C[6];
    C[0] = __half2float(rch[iC * 2 + 0]);                  // row 4sy
    C[5] = __half2float(rch[(iC + 2 * RXW) * 2 + 1]);      // row 4sy+5
    C[1] = val[0]; C[2] = val[1]; C[3] = val[2]; C[4] = val[3];

    float nv[4];
    #pragma unroll
    for (int r = 0; r < 4; r++) {
        float s = bias[r];
        s += g[r][0] * R[r + 2];
        s += g[r][1] * C[r + 2];
        s += g[r][2] * L[r + 2];
        s += g[r][3] * R[r + 1];
        s += g[r][4] * L[r + 1];
        s += g[r][5] * R[r];
        s += g[r][6] * C[r];
        s += g[r][7] * L[r];
        nv[r] = s;
    }
    #pragma unroll
    for (int r = 0; r < 4; r++) val[r] = nv[r];
}

// Store a strip's 4 values into buffer rn (byte-granular at shared words).
__device__ __forceinline__ void strip_store(unsigned int* __restrict__ rn,
                                            int iC, const float val[4])
{
    __half* __restrict__ rh = reinterpret_cast<__half*>(rn);
    rh[iC * 2 + 1] = __float2half_rn(val[0]);             // row 4sy+1 (hi)
    rn[iC + RXW] = pack2(val[1], val[2]);                 // rows 4sy+2,3
    rh[(iC + 2 * RXW) * 2 + 0] = __float2half_rn(val[3]); // row 4sy+4 (lo)
}

__global__ __launch_bounds__(NTH, 3)
void affinity_fused(const float* __restrict__ guid,
                    const float* __restrict__ blur,
                    float* __restrict__ out)
{
    // fp16 exchange buffers: word (p, c) = half2(row 2p, row 2p+1) at col c
    __shared__ unsigned int res[2][PR * RXW];

    const int tid = threadIdx.x;
    const int b   = blockIdx.z;
    const int txi = blockIdx.x;
    const int tyi = blockIdx.y;
    const int ox  = txi * TX;
    const int oy  = tyi * TY;
    // tyi = 11 is interior: its res window max y = 440+45 = 485 < 512 and its
    // gate reads max y = 485 < 512. Only tyi = 12 (rows >= 480-3) clips.
    const bool edge = (txi == 0) | (txi == NTX - 1) | (tyi == 0) | (tyi == NTY - 1);

    const float* __restrict__ blurb = blur + (size_t)b * HH * WW;
    const float* __restrict__ guidb = guid + (size_t)b * 8 * HH * WW;

    // ---- Strip mapping: warp = strip row, lane = gate column (contiguous) ----
    const int sy   = tid >> 5;            // 0..11
    const int sx   = tid & 31;            // gate col 0..31
    const int x    = ox - 3 + sx;         // global x of strip
    const int y0   = oy - 3 + sy * 4;     // global y of strip top
    const int bx   = (ox - 8) & ~3;       // res base col (float4 aligned)
    const int rx   = (ox - 3 - bx) + sx;  // res col index
    const int p0   = 2 * sy;              // first pair-row of strip
    // Hoisted shared-word indices (constant across all iterations)
    const int iC   = p0 * RXW + rx;       // own column, first pair-row
    const int iL   = iC - 1;              // left neighbor column
    const int iR   = iC + 1;              // right neighbor column

    float g[4][8];
    float raw[4];

    if (!edge) {
        // ============== interior fast path (no guards) ==============
        // Gate + raw LDGs first: longest-latency loads front-loaded.
        {
            const float* __restrict__ gb = guidb + (size_t)y0 * WW + x;
            #pragma unroll
            for (int r = 0; r < 4; r++) {
                const float* __restrict__ gr = gb + r * WW;
                g[r][0] = __ldg(gr + 0 * HH * WW + DI0 * WW + DJ0);
                g[r][1] = __ldg(gr + 1 * HH * WW + DI1 * WW + DJ1);
                g[r][2] = __ldg(gr + 2 * HH * WW + DI2 * WW + DJ2);
                g[r][3] = __ldg(gr + 3 * HH * WW + DI3 * WW + DJ3);
                g[r][4] = __ldg(gr + 4 * HH * WW + DI4 * WW + DJ4);
                g[r][5] = __ldg(gr + 5 * HH * WW + DI5 * WW + DJ5);
                g[r][6] = __ldg(gr + 6 * HH * WW + DI6 * WW + DJ6);
                g[r][7] = __ldg(gr + 7 * HH * WW + DI7 * WW + DJ7);
            }
            const float* __restrict__ rb = blurb + (size_t)y0 * WW + x;
            raw[0] = __ldg(rb + 0 * WW);
            raw[1] = __ldg(rb + 1 * WW);
            raw[2] = __ldg(rb + 2 * WW);
            raw[3] = __ldg(rb + 3 * WW);
        }
        // Full-tile init of buf0 (coalesced float4; 275 items < 384 threads)
        if (tid < PR * 11) {
            int p = tid / 11, q = tid % 11;
            const float* __restrict__ base =
                blurb + (size_t)(oy - 4 + 2 * p) * WW + bx + 4 * q;
            float4 a  = *reinterpret_cast<const float4*>(base);
            float4 bb = *reinterpret_cast<const float4*>(base + WW);
            int o = p * RXW + 4 * q;
            res[0][o+0] = pack2(a.x, bb.x);
            res[0][o+1] = pack2(a.y, bb.y);
            res[0][o+2] = pack2(a.z, bb.z);
            res[0][o+3] = pack2(a.w, bb.w);
        }
        // buf1 caps: only pair-rows 0 and 24 are read before being overwritten
        if (tid < 2 * 11) {
            int p = (tid < 11) ? 0 : (PR - 1);
            int q = (tid < 11) ? tid : (tid - 11);
            const float* __restrict__ base =
                blurb + (size_t)(oy - 4 + 2 * p) * WW + bx + 4 * q;
            float4 a  = *reinterpret_cast<const float4*>(base);
            float4 bb = *reinterpret_cast<const float4*>(base + WW);
            int o = p * RXW + 4 * q;
            res[1][o+0] = pack2(a.x, bb.x);
            res[1][o+1] = pack2(a.y, bb.y);
            res[1][o+2] = pack2(a.z, bb.z);
            res[1][o+3] = pack2(a.w, bb.w);
        }
    } else {
        // ======== edge path: clamped addresses + float masks ========
        const int xc = min(max(x, 0), WW - 1);
        #pragma unroll
        for (int r = 0; r < 4; r++) {
            int y  = y0 + r;
            int yc = min(max(y, 0), HH - 1);
            bool pin = ((unsigned)y < HH) & ((unsigned)x < WW);
            float rv = __ldg(&blurb[(size_t)yc * WW + xc]);
            raw[r] = pin ? rv : 0.0f;
            #pragma unroll
            for (int k = 0; k < 8; k++) {
                int yy = y + c_di[k];
                int xx = x + c_dj[k];
                int yyc = min(max(yy, 0), HH - 1);
                int xxc = min(max(xx, 0), WW - 1);
                float v = __ldg(&guidb[((size_t)k * HH + yyc) * WW + xxc]);
                bool m = pin & ((unsigned)yy < HH) & ((unsigned)xx < WW);
                g[r][k] = m ? v : 0.0f;
            }
        }
        if (tid < PR * 11) {
            int p = tid / 11, q = tid % 11;
            float4 a  = ld4_guard(blurb, oy - 4 + 2 * p, bx + 4 * q);
            float4 bb = ld4_guard(blurb, oy - 3 + 2 * p, bx + 4 * q);
            int o = p * RXW + 4 * q;
            res[0][o+0] = pack2(a.x, bb.x);
            res[0][o+1] = pack2(a.y, bb.y);
            res[0][o+2] = pack2(a.z, bb.z);
            res[0][o+3] = pack2(a.w, bb.w);
        }
        if (tid < 2 * 11) {
            int p = (tid < 11) ? 0 : (PR - 1);
            int q = (tid < 11) ? tid : (tid - 11);
            float4 a  = ld4_guard(blurb, oy - 4 + 2 * p, bx + 4 * q);
            float4 bb = ld4_guard(blurb, oy - 3 + 2 * p, bx + 4 * q);
            int o = p * RXW + 4 * q;
            res[1][o+0] = pack2(a.x, bb.x);
            res[1][o+1] = pack2(a.y, bb.y);
            res[1][o+2] = pack2(a.z, bb.z);
            res[1][o+3] = pack2(a.w, bb.w);
        }
    }

    // ---- gate normalization (register-only -> hoisted before barrier) ----
    float bias[4], val[4];
    #pragma unroll
    for (int r = 0; r < 4; r++) {
        float a = 0.f;
        #pragma unroll
        for (int k = 0; k < 8; k++) a += fabsf(g[r][k]);
        float inva = (a > 0.f) ? __fdividef(1.0f, a) : 0.0f;
        float gs = 0.f;
        #pragma unroll
        for (int k = 0; k < 8; k++) { g[r][k] *= inva; gs += g[r][k]; }
        bias[r] = (1.0f - gs) * raw[r];
        val[r]  = raw[r];
    }
    __syncthreads();

    // ---- iterations 0..2: compute, store, barrier (all threads are strips) ----
    #pragma unroll
    for (int t = 0; t < 3; t++) {
        prop_step(res[t & 1], iL, iR, iC, g, bias, val);
        strip_store(res[(t & 1) ^ 1], iC, val);
        __syncthreads();
    }

    // ---- final iteration + output: only warps whose values are read ----
    // (strip row 11 = gate rows 44..47 -> no output rows; no barrier after t=3)
    if (sy < 11) {
        prop_step(res[1], iL, iR, iC, g, bias, val);
        float* __restrict__ outb = out + (size_t)b * HH * WW;
        if (sx >= 3 && sx < 3 + TX && x < WW) {
            #pragma unroll
            for (int r = 0; r < 4; r++) {
                int gy = sy * 4 + r;
                int y  = y0 + r;
                if (gy >= 3 && gy < 3 + TY && (unsigned)y < HH)
                    outb[y * WW + x] = val[r];
            }
        }
    }
}

extern "C" void kernel_launch(void* const* d_in, const int* in_sizes, int n_in,
                              void* d_out, int out_size)
{
    const float* guid = (const float*)d_in[0];
    const float* blur = (const float*)d_in[1];
    int gsz = in_sizes[0];
    int bsz = in_sizes[1];
    if (n_in >= 2 && gsz < bsz) {   // defensive: handle swapped order
        const float* tmp = guid; guid = blur; blur = tmp;
        int t = gsz; gsz = bsz; bsz = t;
    }
    int batch = bsz / (HH * WW);

    dim3 grid(NTX, NTY, batch);
    affinity_fused<<<grid, NTH>>>(guid, blur, (float*)d_out);
}